// round 14
// baseline (speedup 1.0000x reference)
#include <cuda_runtime.h>
#include <cuda_fp16.h>
#include <cstdint>
#include <cstddef>

// Problem dims (fixed by the reference)
#define M_DIM 8192
#define N_DIM 1024
#define K_IN  512
#define K_DIM 1536           // K_IN + 1024 (recurrent)
#define PLANE ((size_t)M_DIM * N_DIM)

// GEMM tiling (legacy HMMA path — tcgen05 PTX rejected by harness target, R9)
// Single-pass fp16 (A is binary => exact; weight rounding 2^-12 => norm rel err ~1.5e-4)
#define BM 128
#define BN 128
#define BK 32
#define PAD 40                       // halves per smem row (32 data + 8 pad)
#define TILE_H (BM * PAD)            // halves per tile (5120 = 10240 B)
#define STAGE_H (2 * TILE_H)         // A + B per stage (20480 B)
#define N_STAGES 4
#define SMEM_BYTES (N_STAGES * STAGE_H * 2)   // 81920 B -> 2 CTAs/SM

// Scratch (no cudaMalloc allowed)
__device__ __half g_A[(size_t)M_DIM * K_DIM];  // ~25.2 MB
__device__ __half g_B[(size_t)N_DIM * K_DIM];  // 3 MB

// ---------------------------------------------------------------------------
// helpers
// ---------------------------------------------------------------------------
__device__ __forceinline__ void cp16(__half* s, const __half* g) {
    uint32_t sa = (uint32_t)__cvta_generic_to_shared(s);
    asm volatile("cp.async.cg.shared.global [%0], [%1], 16;\n" :: "r"(sa), "l"(g));
}
__device__ __forceinline__ void ldm_x4(uint32_t* r, const __half* p) {
    uint32_t a = (uint32_t)__cvta_generic_to_shared(p);
    asm volatile("ldmatrix.sync.aligned.m8n8.x4.shared.b16 {%0,%1,%2,%3}, [%4];\n"
        : "=r"(r[0]), "=r"(r[1]), "=r"(r[2]), "=r"(r[3]) : "r"(a));
}
__device__ __forceinline__ void mma_f16(float* c, const uint32_t* a, const uint32_t* b) {
    asm volatile("mma.sync.aligned.m16n8k16.row.col.f32.f16.f16.f32 "
        "{%0,%1,%2,%3}, {%4,%5,%6,%7}, {%8,%9}, {%0,%1,%2,%3};\n"
        : "+f"(c[0]), "+f"(c[1]), "+f"(c[2]), "+f"(c[3])
        : "r"(a[0]), "r"(a[1]), "r"(a[2]), "r"(a[3]), "r"(b[0]), "r"(b[1]));
}

// ---------------------------------------------------------------------------
// pack kernels: fp16 A = [spikes | z] (exact: values are 0/1), fp16 B = [Win | Wrec]
// ---------------------------------------------------------------------------
__global__ void pack_A_kernel(const float* __restrict__ sp, const float* __restrict__ z) {
    size_t g = (size_t)blockIdx.x * blockDim.x + threadIdx.x;   // one group of 4 cols
    int row = (int)(g / (K_DIM / 4));
    int col = (int)(g % (K_DIM / 4)) * 4;
    float4 v = (col < K_IN)
        ? *(const float4*)(sp + (size_t)row * K_IN + col)
        : *(const float4*)(z  + (size_t)row * (K_DIM - K_IN) + (col - K_IN));
    __half2 p0 = __floats2half2_rn(v.x, v.y);
    __half2 p1 = __floats2half2_rn(v.z, v.w);
    __half2* dst = (__half2*)(g_A + (size_t)row * K_DIM + col);
    dst[0] = p0; dst[1] = p1;
}

__global__ void pack_B_kernel(const float* __restrict__ wi, const float* __restrict__ wr) {
    size_t g = ((size_t)blockIdx.x * blockDim.x + threadIdx.x) * 2;   // two elements
    int row = (int)(g / K_DIM);
    int col = (int)(g % K_DIM);   // even; K_IN even so both cols same source
    float2 w = (col < K_IN)
        ? *(const float2*)(wi + (size_t)row * K_IN + col)
        : *(const float2*)(wr + (size_t)row * (K_DIM - K_IN) + (col - K_IN));
    *(__half2*)(g_B + g) = __floats2half2_rn(w.x, w.y);
}

// ---------------------------------------------------------------------------
// pointwise math (exact fp32, reference op order — no FMA contraction)
// ---------------------------------------------------------------------------
__device__ __forceinline__ void lsnn_pw(float v, float i, float b,
                                        float& z, float& vn, float& bn) {
    float t  = __fadd_rn(-v, i);
    float vd = __fadd_rn(v, __fmul_rn(0.1f, t));
    float bd = __fadd_rn(b, __fmul_rn(1.25e-6f, __fsub_rn(1.0f, b)));
    z  = (__fsub_rn(vd, bd) > 0.0f) ? 1.0f : 0.0f;
    vn = (z > 0.0f) ? 0.0f : vd;
    bn = __fadd_rn(bd, __fmul_rn(__fmul_rn(z, 0.00125f), 1.8f));
}

// ---------------------------------------------------------------------------
// fused GEMM + pointwise:  S = A @ B^T (fp16 in, fp32 accum)
//   epilogue per element: z/v/b planes + i_new = i*0.8 + S
// 128x128 CTA tile, 8 warps of 64x32, 4-stage cp.async ring (3 in flight)
// ---------------------------------------------------------------------------
__global__ void __launch_bounds__(256, 2) lsnn_gemm(const float* __restrict__ Vin,
                                                    const float* __restrict__ Iin,
                                                    const float* __restrict__ Bin,
                                                    float* __restrict__ out) {
    extern __shared__ __align__(16) __half smem[];
    const int tid  = threadIdx.x;
    const int lane = tid & 31;
    const int warp = tid >> 5;
    const int wm   = warp & 1;     // warp row (2)
    const int wn   = warp >> 1;    // warp col (4)
    const int bm   = blockIdx.y;
    const int bn   = blockIdx.x;

    float c[4][4][4];
    #pragma unroll
    for (int a = 0; a < 4; a++)
        #pragma unroll
        for (int b = 0; b < 4; b++)
            #pragma unroll
            for (int d = 0; d < 4; d++) c[a][b][d] = 0.0f;

    auto load_tiles = [&](int kt) {
        __half* As = smem + (kt & (N_STAGES - 1)) * STAGE_H;
        __half* Bs = As + TILE_H;
        const int k0 = kt * BK;
        #pragma unroll
        for (int i = 0; i < 2; i++) {
            int ch  = tid + i * 256;       // 512 16B-chunks per tile
            int row = ch >> 2;
            int cc  = (ch & 3) * 8;        // halves
            cp16(As + row * PAD + cc, g_A + (size_t)(bm * BM + row) * K_DIM + k0 + cc);
            cp16(Bs + row * PAD + cc, g_B + (size_t)(bn * BN + row) * K_DIM + k0 + cc);
        }
        asm volatile("cp.async.commit_group;\n" ::);
    };

    const int KT = K_DIM / BK;   // 48
    load_tiles(0);
    load_tiles(1);
    load_tiles(2);

    for (int kt = 0; kt < KT; ++kt) {
        // need group kt complete: pending <= min(2, KT-1-kt)
        if      (kt + 2 < KT) asm volatile("cp.async.wait_group 2;\n" ::);
        else if (kt + 1 < KT) asm volatile("cp.async.wait_group 1;\n" ::);
        else                  asm volatile("cp.async.wait_group 0;\n" ::);
        __syncthreads();
        if (kt + 3 < KT) load_tiles(kt + 3);   // writes stage (kt+3)&3 == (kt-1)&3

        const __half* As = smem + (kt & (N_STAGES - 1)) * STAGE_H;
        const __half* Bs = As + TILE_H;
        #pragma unroll
        for (int ks = 0; ks < 2; ++ks) {   // two k16 sub-steps per BK=32
            uint32_t af[4][4];
            #pragma unroll
            for (int mi = 0; mi < 4; ++mi) {
                const __half* p = As + (wm * 64 + mi * 16 + (lane & 15)) * PAD
                                     + ks * 16 + (lane >> 4) * 8;
                ldm_x4(af[mi], p);
            }
            // B: two ldm_x4, each covers a 16-col (n) x 16 (k) block = 2 ni frags
            //  M0=[n0-7,klo] M1=[n8-15,klo] M2=[n0-7,khi] M3=[n8-15,khi]
            uint32_t bq[2][4];
            #pragma unroll
            for (int p2 = 0; p2 < 2; ++p2) {
                const __half* pb = Bs + (wn * 32 + p2 * 16 + (lane & 15)) * PAD
                                      + ks * 16 + (lane >> 4) * 8;
                ldm_x4(bq[p2], pb);
            }
            uint32_t bf[4][2];
            #pragma unroll
            for (int p2 = 0; p2 < 2; ++p2) {
                bf[2 * p2 + 0][0] = bq[p2][0]; bf[2 * p2 + 0][1] = bq[p2][2];
                bf[2 * p2 + 1][0] = bq[p2][1]; bf[2 * p2 + 1][1] = bq[p2][3];
            }
            #pragma unroll
            for (int mi = 0; mi < 4; ++mi)
                #pragma unroll
                for (int ni = 0; ni < 4; ++ni)
                    mma_f16(c[mi][ni], af[mi], bf[ni]);
        }
    }

    // ---- fused epilogue: pointwise planes + i_new ----
    #pragma unroll
    for (int mi = 0; mi < 4; ++mi) {
        #pragma unroll
        for (int half = 0; half < 2; ++half) {
            int row = bm * BM + wm * 64 + mi * 16 + (lane >> 2) + half * 8;
            #pragma unroll
            for (int ni = 0; ni < 4; ++ni) {
                int col = bn * BN + wn * 32 + ni * 8 + (lane & 3) * 2;
                size_t idx = (size_t)row * N_DIM + col;
                float2 vv = *(const float2*)(Vin + idx);
                float2 ii = *(const float2*)(Iin + idx);
                float2 bb = *(const float2*)(Bin + idx);
                float z0, vn0, bn0, z1, vn1, bn1;
                lsnn_pw(vv.x, ii.x, bb.x, z0, vn0, bn0);
                lsnn_pw(vv.y, ii.y, bb.y, z1, vn1, bn1);
                float2 zz = {z0, z1};
                float2 vo = {vn0, vn1};
                float2 io = {fmaf(-0.2f, ii.x, ii.x) + c[mi][ni][half * 2 + 0],
                             fmaf(-0.2f, ii.y, ii.y) + c[mi][ni][half * 2 + 1]};
                float2 bo = {bn0, bn1};
                *(float2*)(out + idx)             = zz;   // plane 0: z_new
                *(float2*)(out + PLANE + idx)     = vo;   // plane 1: v_new
                *(float2*)(out + 2 * PLANE + idx) = io;   // plane 2: i_new
                *(float2*)(out + 3 * PLANE + idx) = bo;   // plane 3: b_new
            }
        }
    }
}

// ---------------------------------------------------------------------------
// entry
// ---------------------------------------------------------------------------
extern "C" void kernel_launch(void* const* d_in, const int* in_sizes, int n_in,
                              void* d_out, int out_size) {
    const float* spikes = (const float*)d_in[0];   // [8192, 512]
    const float* z      = (const float*)d_in[1];   // [8192, 1024]
    const float* v      = (const float*)d_in[2];   // [8192, 1024]
    const float* i_     = (const float*)d_in[3];   // [8192, 1024]
    const float* b      = (const float*)d_in[4];   // [8192, 1024]
    const float* wi     = (const float*)d_in[5];   // [1024, 512]
    const float* wr     = (const float*)d_in[6];   // [1024, 1024]
    float* out = (float*)d_out;                    // [4, 8192, 1024]

    cudaFuncSetAttribute(lsnn_gemm, cudaFuncAttributeMaxDynamicSharedMemorySize, SMEM_BYTES);

    pack_A_kernel<<<(M_DIM * K_DIM / 4) / 256, 256>>>(spikes, z);
    pack_B_kernel<<<(N_DIM * K_DIM / 2) / 256, 256>>>(wi, wr);

    dim3 grid(N_DIM / BN, M_DIM / BM);   // (8, 64)
    lsnn_gemm<<<grid, 256, SMEM_BYTES>>>(v, i_, b, out);
}

// round 15
// speedup vs baseline: 1.4753x; 1.4753x over previous
#include <cuda_runtime.h>
#include <cuda_fp16.h>
#include <cstdint>
#include <cstddef>

// Problem dims (fixed by the reference)
#define M_DIM 8192
#define N_DIM 1024
#define K_IN  512
#define K_DIM 1536           // K_IN + 1024 (recurrent)
#define PLANE ((size_t)M_DIM * N_DIM)

// GEMM tiling (legacy HMMA path — tcgen05 PTX rejected by harness target, R9)
// fp16 single-pass: A binary => exact; weight rounding 2^-12 => rel_err ~2e-4 (measured R14)
#define BM 128
#define BN 128
#define BK 64                        // halves per stage (128 B rows)
#define PAD 72                       // halves per smem row (64 data + 8 pad; ldmatrix conflict-free)
#define TILE_H (BM * PAD)            // 9216 halves = 18432 B per tile
#define STAGE_H (2 * TILE_H)         // A + B per stage (36864 B)
#define N_STAGES 3
#define SMEM_BYTES (N_STAGES * STAGE_H * 2)   // 110592 B -> 2 CTAs/SM (216KB/SM)

// Scratch (no cudaMalloc allowed)
__device__ __half g_A[(size_t)M_DIM * K_DIM];  // ~25.2 MB
__device__ __half g_B[(size_t)N_DIM * K_DIM];  // 3 MB

// ---------------------------------------------------------------------------
// helpers
// ---------------------------------------------------------------------------
__device__ __forceinline__ void cp16(__half* s, const __half* g) {
    uint32_t sa = (uint32_t)__cvta_generic_to_shared(s);
    asm volatile("cp.async.cg.shared.global [%0], [%1], 16;\n" :: "r"(sa), "l"(g));
}
__device__ __forceinline__ void ldm_x4(uint32_t* r, const __half* p) {
    uint32_t a = (uint32_t)__cvta_generic_to_shared(p);
    asm volatile("ldmatrix.sync.aligned.m8n8.x4.shared.b16 {%0,%1,%2,%3}, [%4];\n"
        : "=r"(r[0]), "=r"(r[1]), "=r"(r[2]), "=r"(r[3]) : "r"(a));
}
__device__ __forceinline__ void mma_f16(float* c, const uint32_t* a, const uint32_t* b) {
    asm volatile("mma.sync.aligned.m16n8k16.row.col.f32.f16.f16.f32 "
        "{%0,%1,%2,%3}, {%4,%5,%6,%7}, {%8,%9}, {%0,%1,%2,%3};\n"
        : "+f"(c[0]), "+f"(c[1]), "+f"(c[2]), "+f"(c[3])
        : "r"(a[0]), "r"(a[1]), "r"(a[2]), "r"(a[3]), "r"(b[0]), "r"(b[1]));
}

// ---------------------------------------------------------------------------
// pack kernels: fp16 A = [spikes | z] (exact: values are 0/1), fp16 B = [Win | Wrec]
// ---------------------------------------------------------------------------
__global__ void pack_A_kernel(const float* __restrict__ sp, const float* __restrict__ z) {
    size_t g = (size_t)blockIdx.x * blockDim.x + threadIdx.x;   // one group of 4 cols
    int row = (int)(g / (K_DIM / 4));
    int col = (int)(g % (K_DIM / 4)) * 4;
    float4 v = (col < K_IN)
        ? *(const float4*)(sp + (size_t)row * K_IN + col)
        : *(const float4*)(z  + (size_t)row * (K_DIM - K_IN) + (col - K_IN));
    __half2 p0 = __floats2half2_rn(v.x, v.y);
    __half2 p1 = __floats2half2_rn(v.z, v.w);
    __half2* dst = (__half2*)(g_A + (size_t)row * K_DIM + col);
    dst[0] = p0; dst[1] = p1;
}

__global__ void pack_B_kernel(const float* __restrict__ wi, const float* __restrict__ wr) {
    size_t g = ((size_t)blockIdx.x * blockDim.x + threadIdx.x) * 2;   // two elements
    int row = (int)(g / K_DIM);
    int col = (int)(g % K_DIM);   // even; K_IN even so both cols same source
    float2 w = (col < K_IN)
        ? *(const float2*)(wi + (size_t)row * K_IN + col)
        : *(const float2*)(wr + (size_t)row * (K_DIM - K_IN) + (col - K_IN));
    *(__half2*)(g_B + g) = __floats2half2_rn(w.x, w.y);
}

// ---------------------------------------------------------------------------
// pointwise math (exact fp32, reference op order — no FMA contraction)
// ---------------------------------------------------------------------------
__device__ __forceinline__ void lsnn_pw(float v, float i, float b,
                                        float& z, float& vn, float& bn) {
    float t  = __fadd_rn(-v, i);
    float vd = __fadd_rn(v, __fmul_rn(0.1f, t));
    float bd = __fadd_rn(b, __fmul_rn(1.25e-6f, __fsub_rn(1.0f, b)));
    z  = (__fsub_rn(vd, bd) > 0.0f) ? 1.0f : 0.0f;
    vn = (z > 0.0f) ? 0.0f : vd;
    bn = __fadd_rn(bd, __fmul_rn(__fmul_rn(z, 0.00125f), 1.8f));
}

// ---------------------------------------------------------------------------
// fused GEMM + pointwise:  S = A @ B^T (fp16 in, fp32 accum)
// 128x128 CTA tile, 8 warps of 64x32, BK=64, 3-stage ring (prefetch 2 iters),
// register double-buffered fragments (LDSM for step s+1 overlaps MMA of step s)
// ---------------------------------------------------------------------------
__global__ void __launch_bounds__(256, 2) lsnn_gemm(const float* __restrict__ Vin,
                                                    const float* __restrict__ Iin,
                                                    const float* __restrict__ Bin,
                                                    float* __restrict__ out) {
    extern __shared__ __align__(16) __half smem[];
    const int tid  = threadIdx.x;
    const int lane = tid & 31;
    const int warp = tid >> 5;
    const int wm   = warp & 1;     // warp row (2)
    const int wn   = warp >> 1;    // warp col (4)
    const int bm   = blockIdx.y;
    const int bn   = blockIdx.x;

    float c[4][4][4];
    #pragma unroll
    for (int a = 0; a < 4; a++)
        #pragma unroll
        for (int b = 0; b < 4; b++)
            #pragma unroll
            for (int d = 0; d < 4; d++) c[a][b][d] = 0.0f;

    auto load_tiles = [&](int kt) {
        __half* As = smem + (kt % N_STAGES) * STAGE_H;
        __half* Bs = As + TILE_H;
        const int k0 = kt * BK;
        // per tile: 128 rows x 8 chunks(16B) = 1024 chunks, 256 threads -> 4 each
        #pragma unroll
        for (int i = 0; i < 4; i++) {
            int ch  = tid + i * 256;
            int row = ch >> 3;
            int cc  = (ch & 7) * 8;        // halves
            cp16(As + row * PAD + cc, g_A + (size_t)(bm * BM + row) * K_DIM + k0 + cc);
        }
        #pragma unroll
        for (int i = 0; i < 4; i++) {
            int ch  = tid + i * 256;
            int row = ch >> 3;
            int cc  = (ch & 7) * 8;
            cp16(Bs + row * PAD + cc, g_B + (size_t)(bn * BN + row) * K_DIM + k0 + cc);
        }
        asm volatile("cp.async.commit_group;\n" ::);
    };

    // fragment loader for k16 sub-step s (0..3) of the current stage
    auto load_frags = [&](const __half* As, const __half* Bs, int s,
                          uint32_t af[4][4], uint32_t bf[4][2]) {
        #pragma unroll
        for (int mi = 0; mi < 4; ++mi) {
            const __half* p = As + (wm * 64 + mi * 16 + (lane & 15)) * PAD
                                 + s * 16 + (lane >> 4) * 8;
            ldm_x4(af[mi], p);
        }
        uint32_t bq[2][4];
        #pragma unroll
        for (int p2 = 0; p2 < 2; ++p2) {
            const __half* pb = Bs + (wn * 32 + p2 * 16 + (lane & 15)) * PAD
                                  + s * 16 + (lane >> 4) * 8;
            ldm_x4(bq[p2], pb);
        }
        // M0=[n0-7,klo] M1=[n8-15,klo] M2=[n0-7,khi] M3=[n8-15,khi]
        #pragma unroll
        for (int p2 = 0; p2 < 2; ++p2) {
            bf[2 * p2 + 0][0] = bq[p2][0]; bf[2 * p2 + 0][1] = bq[p2][2];
            bf[2 * p2 + 1][0] = bq[p2][1]; bf[2 * p2 + 1][1] = bq[p2][3];
        }
    };

    const int KT = K_DIM / BK;   // 24
    load_tiles(0);
    load_tiles(1);

    for (int kt = 0; kt < KT; ++kt) {
        if (kt + 1 < KT) asm volatile("cp.async.wait_group 1;\n" ::);
        else             asm volatile("cp.async.wait_group 0;\n" ::);
        __syncthreads();
        if (kt + 2 < KT) load_tiles(kt + 2);   // stage (kt+2)%3 == (kt-1)%3, already consumed

        const __half* As = smem + (kt % N_STAGES) * STAGE_H;
        const __half* Bs = As + TILE_H;

        uint32_t af[2][4][4], bf[2][4][2];
        load_frags(As, Bs, 0, af[0], bf[0]);
        #pragma unroll
        for (int s = 0; s < 4; ++s) {          // 4 k16 sub-steps per BK=64
            if (s < 3) load_frags(As, Bs, s + 1, af[(s + 1) & 1], bf[(s + 1) & 1]);
            uint32_t (*a)[4] = af[s & 1];
            uint32_t (*b)[2] = bf[s & 1];
            #pragma unroll
            for (int mi = 0; mi < 4; ++mi)
                #pragma unroll
                for (int ni = 0; ni < 4; ++ni)
                    mma_f16(c[mi][ni], a[mi], b[ni]);
        }
    }

    // ---- fused epilogue: pointwise planes + i_new ----
    #pragma unroll
    for (int mi = 0; mi < 4; ++mi) {
        #pragma unroll
        for (int half = 0; half < 2; ++half) {
            int row = bm * BM + wm * 64 + mi * 16 + (lane >> 2) + half * 8;
            #pragma unroll
            for (int ni = 0; ni < 4; ++ni) {
                int col = bn * BN + wn * 32 + ni * 8 + (lane & 3) * 2;
                size_t idx = (size_t)row * N_DIM + col;
                float2 vv = *(const float2*)(Vin + idx);
                float2 ii = *(const float2*)(Iin + idx);
                float2 bb = *(const float2*)(Bin + idx);
                float z0, vn0, bn0, z1, vn1, bn1;
                lsnn_pw(vv.x, ii.x, bb.x, z0, vn0, bn0);
                lsnn_pw(vv.y, ii.y, bb.y, z1, vn1, bn1);
                float2 zz = {z0, z1};
                float2 vo = {vn0, vn1};
                float2 io = {fmaf(-0.2f, ii.x, ii.x) + c[mi][ni][half * 2 + 0],
                             fmaf(-0.2f, ii.y, ii.y) + c[mi][ni][half * 2 + 1]};
                float2 bo = {bn0, bn1};
                *(float2*)(out + idx)             = zz;   // plane 0: z_new
                *(float2*)(out + PLANE + idx)     = vo;   // plane 1: v_new
                *(float2*)(out + 2 * PLANE + idx) = io;   // plane 2: i_new
                *(float2*)(out + 3 * PLANE + idx) = bo;   // plane 3: b_new
            }
        }
    }
}

// ---------------------------------------------------------------------------
// entry
// ---------------------------------------------------------------------------
extern "C" void kernel_launch(void* const* d_in, const int* in_sizes, int n_in,
                              void* d_out, int out_size) {
    const float* spikes = (const float*)d_in[0];   // [8192, 512]
    const float* z      = (const float*)d_in[1];   // [8192, 1024]
    const float* v      = (const float*)d_in[2];   // [8192, 1024]
    const float* i_     = (const float*)d_in[3];   // [8192, 1024]
    const float* b      = (const float*)d_in[4];   // [8192, 1024]
    const float* wi     = (const float*)d_in[5];   // [1024, 512]
    const float* wr     = (const float*)d_in[6];   // [1024, 1024]
    float* out = (float*)d_out;                    // [4, 8192, 1024]

    cudaFuncSetAttribute(lsnn_gemm, cudaFuncAttributeMaxDynamicSharedMemorySize, SMEM_BYTES);

    pack_A_kernel<<<(M_DIM * K_DIM / 4) / 256, 256>>>(spikes, z);
    pack_B_kernel<<<(N_DIM * K_DIM / 2) / 256, 256>>>(wi, wr);

    dim3 grid(N_DIM / BN, M_DIM / BM);   // (8, 64)
    lsnn_gemm<<<grid, 256, SMEM_BYTES>>>(v, i_, b, out);
}

// round 16
// speedup vs baseline: 1.4909x; 1.0106x over previous
#include <cuda_runtime.h>
#include <cuda_fp16.h>
#include <cstdint>
#include <cstddef>

// Problem dims (fixed by the reference)
#define M_DIM 8192
#define N_DIM 1024
#define K_IN  512
#define K_DIM 1536           // K_IN + 1024 (recurrent)
#define PLANE ((size_t)M_DIM * N_DIM)

// GEMM tiling (legacy HMMA path — tcgen05 PTX rejected by harness target, R9)
// fp16 single-pass: A binary => exact; weight rounding 2^-12 => rel_err ~2e-4 (measured)
#define BM 128
#define BN 128
#define BK 64                        // halves per stage row chunk
#define PAD 72                       // halves per smem row (64 data + 8 pad; ldmatrix conflict-free)
#define TILE_H (BM * PAD)            // 9216 halves = 18432 B per tile
#define STAGE_H (2 * TILE_H)         // A + B per stage (36864 B)
#define N_STAGES 3
#define SMEM_BYTES (N_STAGES * STAGE_H * 2)   // 110592 B -> 2 CTAs/SM

#define KT_PER_TILE (K_DIM / BK)     // 24
#define N_TILES ((M_DIM / BM) * (N_DIM / BN))  // 512
#define N_CTAS 296                   // 2 per SM x 148 SMs

// Scratch (no cudaMalloc allowed)
__device__ __half g_A[(size_t)M_DIM * K_DIM];  // ~25.2 MB
__device__ __half g_B[(size_t)N_DIM * K_DIM];  // 3 MB

// ---------------------------------------------------------------------------
// helpers
// ---------------------------------------------------------------------------
__device__ __forceinline__ void cp16(__half* s, const __half* g) {
    uint32_t sa = (uint32_t)__cvta_generic_to_shared(s);
    asm volatile("cp.async.cg.shared.global [%0], [%1], 16;\n" :: "r"(sa), "l"(g));
}
__device__ __forceinline__ void ldm_x4(uint32_t* r, const __half* p) {
    uint32_t a = (uint32_t)__cvta_generic_to_shared(p);
    asm volatile("ldmatrix.sync.aligned.m8n8.x4.shared.b16 {%0,%1,%2,%3}, [%4];\n"
        : "=r"(r[0]), "=r"(r[1]), "=r"(r[2]), "=r"(r[3]) : "r"(a));
}
__device__ __forceinline__ void mma_f16(float* c, const uint32_t* a, const uint32_t* b) {
    asm volatile("mma.sync.aligned.m16n8k16.row.col.f32.f16.f16.f32 "
        "{%0,%1,%2,%3}, {%4,%5,%6,%7}, {%8,%9}, {%0,%1,%2,%3};\n"
        : "+f"(c[0]), "+f"(c[1]), "+f"(c[2]), "+f"(c[3])
        : "r"(a[0]), "r"(a[1]), "r"(a[2]), "r"(a[3]), "r"(b[0]), "r"(b[1]));
}

// ---------------------------------------------------------------------------
// merged pack kernel: fp16 A = [spikes | z] (exact), fp16 B = [Win | Wrec]
// blocks [0, 12288): A (4 cols/thread). blocks [12288, 15360): B (2 elems/thread).
// ---------------------------------------------------------------------------
#define PACK_A_BLOCKS (M_DIM * K_DIM / 4 / 256)          // 12288
#define PACK_B_BLOCKS (N_DIM * K_DIM / 2 / 256)          // 3072

__global__ void pack_kernel(const float* __restrict__ sp, const float* __restrict__ z,
                            const float* __restrict__ wi, const float* __restrict__ wr) {
    int blk = blockIdx.x;
    if (blk < PACK_A_BLOCKS) {
        size_t g = (size_t)blk * blockDim.x + threadIdx.x;   // one group of 4 cols
        int row = (int)(g / (K_DIM / 4));
        int col = (int)(g % (K_DIM / 4)) * 4;
        float4 v = (col < K_IN)
            ? *(const float4*)(sp + (size_t)row * K_IN + col)
            : *(const float4*)(z  + (size_t)row * (K_DIM - K_IN) + (col - K_IN));
        __half2 p0 = __floats2half2_rn(v.x, v.y);
        __half2 p1 = __floats2half2_rn(v.z, v.w);
        __half2* dst = (__half2*)(g_A + (size_t)row * K_DIM + col);
        dst[0] = p0; dst[1] = p1;
    } else {
        size_t g = ((size_t)(blk - PACK_A_BLOCKS) * blockDim.x + threadIdx.x) * 2;
        int row = (int)(g / K_DIM);
        int col = (int)(g % K_DIM);   // even; K_IN even so both cols same source
        float2 w = (col < K_IN)
            ? *(const float2*)(wi + (size_t)row * K_IN + col)
            : *(const float2*)(wr + (size_t)row * (K_DIM - K_IN) + (col - K_IN));
        *(__half2*)(g_B + g) = __floats2half2_rn(w.x, w.y);
    }
}

// ---------------------------------------------------------------------------
// pointwise math (exact fp32, reference op order — no FMA contraction)
// ---------------------------------------------------------------------------
__device__ __forceinline__ void lsnn_pw(float v, float i, float b,
                                        float& z, float& vn, float& bn) {
    float t  = __fadd_rn(-v, i);
    float vd = __fadd_rn(v, __fmul_rn(0.1f, t));
    float bd = __fadd_rn(b, __fmul_rn(1.25e-6f, __fsub_rn(1.0f, b)));
    z  = (__fsub_rn(vd, bd) > 0.0f) ? 1.0f : 0.0f;
    vn = (z > 0.0f) ? 0.0f : vd;
    bn = __fadd_rn(bd, __fmul_rn(__fmul_rn(z, 0.00125f), 1.8f));
}

// ---------------------------------------------------------------------------
// persistent fused GEMM + pointwise:  S = A @ B^T (fp16 in, fp32 accum)
// 296 persistent CTAs (2/SM). Each handles 1-2 tiles of 128x128. Flattened
// (tile x kt) pipeline: cp.async prefetch runs 2 iters ahead ACROSS tile
// boundaries, so the epilogue of tile t overlaps the first loads of tile t+1.
// ---------------------------------------------------------------------------
__global__ void __launch_bounds__(256, 2) lsnn_gemm(const float* __restrict__ Vin,
                                                    const float* __restrict__ Iin,
                                                    const float* __restrict__ Bin,
                                                    float* __restrict__ out) {
    extern __shared__ __align__(16) __half smem[];
    const int tid  = threadIdx.x;
    const int lane = tid & 31;
    const int warp = tid >> 5;
    const int wm   = warp & 1;     // warp row (2)
    const int wn   = warp >> 1;    // warp col (4)

    int tiles[2];
    tiles[0] = blockIdx.x;
    tiles[1] = blockIdx.x + N_CTAS;
    const int nt    = (tiles[1] < N_TILES) ? 2 : 1;
    const int total = nt * KT_PER_TILE;

    float c[4][4][4];
    #pragma unroll
    for (int a = 0; a < 4; a++)
        #pragma unroll
        for (int b = 0; b < 4; b++)
            #pragma unroll
            for (int d = 0; d < 4; d++) c[a][b][d] = 0.0f;

    // prefetch one flattened iteration g = ti*24 + kt into stage g%3
    auto pf = [&](int g) {
        int tile = tiles[g / KT_PER_TILE];
        int kt   = g % KT_PER_TILE;
        int pbm  = tile >> 3;
        int pbn  = tile & 7;
        __half* As = smem + (g % N_STAGES) * STAGE_H;
        __half* Bs = As + TILE_H;
        const int k0 = kt * BK;
        #pragma unroll
        for (int i = 0; i < 4; i++) {
            int ch  = tid + i * 256;
            int row = ch >> 3;
            int cc  = (ch & 7) * 8;        // halves
            cp16(As + row * PAD + cc, g_A + (size_t)(pbm * BM + row) * K_DIM + k0 + cc);
        }
        #pragma unroll
        for (int i = 0; i < 4; i++) {
            int ch  = tid + i * 256;
            int row = ch >> 3;
            int cc  = (ch & 7) * 8;
            cp16(Bs + row * PAD + cc, g_B + (size_t)(pbn * BN + row) * K_DIM + k0 + cc);
        }
        asm volatile("cp.async.commit_group;\n" ::);
    };

    // fragment loader for k16 sub-step s (0..3) of the given stage
    auto load_frags = [&](const __half* As, const __half* Bs, int s,
                          uint32_t af[4][4], uint32_t bf[4][2]) {
        #pragma unroll
        for (int mi = 0; mi < 4; ++mi) {
            const __half* p = As + (wm * 64 + mi * 16 + (lane & 15)) * PAD
                                 + s * 16 + (lane >> 4) * 8;
            ldm_x4(af[mi], p);
        }
        uint32_t bq[2][4];
        #pragma unroll
        for (int p2 = 0; p2 < 2; ++p2) {
            const __half* pb = Bs + (wn * 32 + p2 * 16 + (lane & 15)) * PAD
                                  + s * 16 + (lane >> 4) * 8;
            ldm_x4(bq[p2], pb);
        }
        #pragma unroll
        for (int p2 = 0; p2 < 2; ++p2) {
            bf[2 * p2 + 0][0] = bq[p2][0]; bf[2 * p2 + 0][1] = bq[p2][2];
            bf[2 * p2 + 1][0] = bq[p2][1]; bf[2 * p2 + 1][1] = bq[p2][3];
        }
    };

    pf(0);
    if (total > 1) pf(1);

    for (int g = 0; g < total; ++g) {
        if (g + 1 < total) asm volatile("cp.async.wait_group 1;\n" ::);
        else               asm volatile("cp.async.wait_group 0;\n" ::);
        __syncthreads();
        if (g + 2 < total) pf(g + 2);   // stage (g+2)%3: last read at iter g-1, done

        const __half* As = smem + (g % N_STAGES) * STAGE_H;
        const __half* Bs = As + TILE_H;

        uint32_t af[2][4][4], bf[2][4][2];
        load_frags(As, Bs, 0, af[0], bf[0]);
        #pragma unroll
        for (int s = 0; s < 4; ++s) {          // 4 k16 sub-steps per BK=64
            if (s < 3) load_frags(As, Bs, s + 1, af[(s + 1) & 1], bf[(s + 1) & 1]);
            uint32_t (*a)[4] = af[s & 1];
            uint32_t (*b)[2] = bf[s & 1];
            #pragma unroll
            for (int mi = 0; mi < 4; ++mi)
                #pragma unroll
                for (int ni = 0; ni < 4; ++ni)
                    mma_f16(c[mi][ni], a[mi], b[ni]);
        }

        // ---- tile complete: fused epilogue (overlaps next tile's prefetch) ----
        if ((g % KT_PER_TILE) == KT_PER_TILE - 1) {
            int tile = tiles[g / KT_PER_TILE];
            int ebm  = tile >> 3;
            int ebn  = tile & 7;
            #pragma unroll
            for (int mi = 0; mi < 4; ++mi) {
                #pragma unroll
                for (int half = 0; half < 2; ++half) {
                    int row = ebm * BM + wm * 64 + mi * 16 + (lane >> 2) + half * 8;
                    size_t base = (size_t)row * N_DIM + ebn * BN + wn * 32 + (lane & 3) * 2;
                    // batch all loads first (MLP)
                    float2 vv[4], ii[4], bb[4];
                    #pragma unroll
                    for (int ni = 0; ni < 4; ++ni) {
                        size_t idx = base + ni * 8;
                        vv[ni] = *(const float2*)(Vin + idx);
                        ii[ni] = *(const float2*)(Iin + idx);
                        bb[ni] = *(const float2*)(Bin + idx);
                    }
                    #pragma unroll
                    for (int ni = 0; ni < 4; ++ni) {
                        size_t idx = base + ni * 8;
                        float z0, vn0, bn0, z1, vn1, bn1;
                        lsnn_pw(vv[ni].x, ii[ni].x, bb[ni].x, z0, vn0, bn0);
                        lsnn_pw(vv[ni].y, ii[ni].y, bb[ni].y, z1, vn1, bn1);
                        float2 zz = {z0, z1};
                        float2 vo = {vn0, vn1};
                        float2 io = {fmaf(-0.2f, ii[ni].x, ii[ni].x) + c[mi][ni][half * 2 + 0],
                                     fmaf(-0.2f, ii[ni].y, ii[ni].y) + c[mi][ni][half * 2 + 1]};
                        float2 bo = {bn0, bn1};
                        *(float2*)(out + idx)             = zz;   // plane 0: z_new
                        *(float2*)(out + PLANE + idx)     = vo;   // plane 1: v_new
                        *(float2*)(out + 2 * PLANE + idx) = io;   // plane 2: i_new
                        *(float2*)(out + 3 * PLANE + idx) = bo;   // plane 3: b_new
                    }
                }
            }
            // reset accumulators for next tile
            #pragma unroll
            for (int a = 0; a < 4; a++)
                #pragma unroll
                for (int b = 0; b < 4; b++)
                    #pragma unroll
                    for (int d = 0; d < 4; d++) c[a][b][d] = 0.0f;
        }
    }
}

// ---------------------------------------------------------------------------
// entry
// ---------------------------------------------------------------------------
extern "C" void kernel_launch(void* const* d_in, const int* in_sizes, int n_in,
                              void* d_out, int out_size) {
    const float* spikes = (const float*)d_in[0];   // [8192, 512]
    const float* z      = (const float*)d_in[1];   // [8192, 1024]
    const float* v      = (const float*)d_in[2];   // [8192, 1024]
    const float* i_     = (const float*)d_in[3];   // [8192, 1024]
    const float* b      = (const float*)d_in[4];   // [8192, 1024]
    const float* wi     = (const float*)d_in[5];   // [1024, 512]
    const float* wr     = (const float*)d_in[6];   // [1024, 1024]
    float* out = (float*)d_out;                    // [4, 8192, 1024]

    cudaFuncSetAttribute(lsnn_gemm, cudaFuncAttributeMaxDynamicSharedMemorySize, SMEM_BYTES);

    pack_kernel<<<PACK_A_BLOCKS + PACK_B_BLOCKS, 256>>>(spikes, z, wi, wr);
    lsnn_gemm<<<N_CTAS, 256, SMEM_BYTES>>>(v, i_, b, out);
}